// round 7
// baseline (speedup 1.0000x reference)
#include <cuda_runtime.h>
#include <math.h>

#define TILE_W 16
#define TILE_H 8
#define NTHREADS 128
#define NW 4                 // warps per block
#define MAX_G 2048
#define CHUNK 512
#define RPW (CHUNK / NW)     // 128 gaussians per warp per chunk
#define ROUNDS (RPW / 32)    // 4 ballot rounds
#define MAH_CUT 37.0f        // density threshold ~ exp(-18.5)
#define LOG2E 1.4426950408889634f

// ---- device scratch (depth-sorted, packed) ----
__device__ float4 g_pA[MAX_G];   // mx, my, cullR^2, a' (= -0.5*iA*log2e)
__device__ float4 g_pB[MAX_G];   // b' (= -iB*log2e), c' (= -0.5*iC*log2e), log2(opac), colR
__device__ float2 g_pC[MAX_G];   // colG, colB

__device__ __forceinline__ float ex2(float x) {
    float r;
    asm("ex2.approx.ftz.f32 %0, %1;" : "=f"(r) : "f"(x));
    return r;
}

// ---- 1) prep: warp-per-gaussian stable rank + preprocess + scatter ----
__global__ void __launch_bounds__(256) prep_kernel(
        const float* __restrict__ means,
        const float* __restrict__ log_scale,
        const float* __restrict__ rot,
        const float* __restrict__ colour_logits,
        const float* __restrict__ opacity_logit,
        const float* __restrict__ depth,
        int G) {
    __shared__ float sd[MAX_G];
    for (int j = threadIdx.x; j < G; j += blockDim.x) sd[j] = depth[j];
    __syncthreads();

    int w    = threadIdx.x >> 5;
    int lane = threadIdx.x & 31;
    int i = blockIdx.x * 8 + w;
    if (i >= G) return;

    float di = sd[i];
    int r = 0;
    for (int j = lane; j < G; j += 32) {
        float dj = sd[j];
        r += (dj < di) || (dj == di && j < i);
    }
    r = __reduce_add_sync(0xffffffffu, r);

    if (lane == 0) {
        float s2x = __expf(2.f * log_scale[2 * i + 0]);
        float s2y = __expf(2.f * log_scale[2 * i + 1]);
        float s, c;
        __sincosf(rot[i], &s, &c);

        float ca = c * c * s2x + s * s * s2y;
        float cb = c * s * (s2x - s2y);
        float cd = s * s * s2x + c * c * s2y;
        float det = ca * cd - cb * cb;
        float inv = 1.f / det;
        float iA = cd * inv;
        float iB = -cb * inv;
        float iC = ca * inv;

        float opac = 1.f / (1.f + __expf(-opacity_logit[i]));
        float cr  = 1.f / (1.f + __expf(-colour_logits[3 * i + 0]));
        float cg  = 1.f / (1.f + __expf(-colour_logits[3 * i + 1]));
        float cbl = 1.f / (1.f + __expf(-colour_logits[3 * i + 2]));

        float tr = 0.5f * (ca + cd);
        float lmax = tr + sqrtf(fmaxf(tr * tr - det, 0.f));

        g_pA[r] = make_float4(means[2 * i + 0], means[2 * i + 1],
                              MAH_CUT * lmax, -0.5f * iA * LOG2E);
        g_pB[r] = make_float4(-iB * LOG2E, -0.5f * iC * LOG2E,
                              __log2f(opac), cr);
        g_pC[r] = make_float2(cg, cbl);
    }
}

// ---- 2) raster: block per 16x8 tile, 128 threads ----
__global__ void __launch_bounds__(NTHREADS) raster_kernel(int W, int H, int ntx, int G,
                                                          float* __restrict__ out) {
    int tile = blockIdx.x;
    int tx = tile % ntx, ty = tile / ntx;
    int lx = threadIdx.x & (TILE_W - 1);
    int ly = threadIdx.x >> 4;
    int px = tx * TILE_W + lx;
    int py = ty * TILE_H + ly;
    float fx = (float)px, fy = (float)py;

    float x0 = (float)(tx * TILE_W);
    float y0 = (float)(ty * TILE_H);
    float x1 = x0 + (float)(TILE_W - 1);
    float y1 = y0 + (float)(TILE_H - 1);

    int wid  = threadIdx.x >> 5;
    int lane = threadIdx.x & 31;
    unsigned lmask = (1u << lane) - 1u;

    __shared__ float4 sA[CHUNK];
    __shared__ float4 sB[CHUNK];
    __shared__ float2 sC[CHUNK];
    __shared__ int    scnt[NW];

    float T = 1.f, accR = 0.f, accG = 0.f, accB = 0.f;

    for (int c0 = 0; c0 < G; c0 += CHUNK) {
        int gw = c0 + wid * RPW;

        // prefetch cull data: one LDG.128 per gaussian
        float4 Ar[ROUNDS];
#pragma unroll
        for (int r = 0; r < ROUNDS; r++) {
            int g = gw + r * 32 + lane;
            Ar[r] = (g < G) ? g_pA[g] : make_float4(1e30f, 1e30f, -1.f, 0.f);
        }

        // hit tests (registers only)
        bool hr[ROUNDS];
#pragma unroll
        for (int r = 0; r < ROUNDS; r++) {
            float ddx = fmaxf(fmaxf(x0 - Ar[r].x, Ar[r].x - x1), 0.f);
            float ddy = fmaxf(fmaxf(y0 - Ar[r].y, Ar[r].y - y1), 0.f);
            hr[r] = (ddx * ddx + ddy * ddy) <= Ar[r].z;
        }

        // issue predicated B/C loads early so latency overlaps prefix math
        float4 Br[ROUNDS];
        float2 Cr[ROUNDS];
#pragma unroll
        for (int r = 0; r < ROUNDS; r++) {
            if (hr[r]) {
                int g = gw + r * 32 + lane;
                Br[r] = g_pB[g];
                Cr[r] = g_pC[g];
            }
        }

        // ballots + in-warp offsets
        unsigned mask[ROUNDS];
        int offr[ROUNDS];
        int cnt = 0;
#pragma unroll
        for (int r = 0; r < ROUNDS; r++) {
            mask[r] = __ballot_sync(0xffffffffu, hr[r]);
            offr[r] = cnt;
            cnt += __popc(mask[r]);
        }
        if (lane == 0) scnt[wid] = cnt;
        __syncthreads();   // also guards prev-chunk composite reads

        int woff = 0, total = 0;
#pragma unroll
        for (int w = 0; w < NW; w++) {
            int cw = scnt[w];
            woff += (w < wid) ? cw : 0;
            total += cw;
        }

        // scatter compacted data (depth order preserved)
#pragma unroll
        for (int r = 0; r < ROUNDS; r++) {
            if (hr[r]) {
                int idx = woff + offr[r] + __popc(mask[r] & lmask);
                sA[idx] = Ar[r];
                sB[idx] = Br[r];
                sC[idx] = Cr[r];
            }
        }
        __syncthreads();

        // flat branch-free composite
#pragma unroll 4
        for (int j = 0; j < total; j++) {
            float4 Aj = sA[j];
            float4 Bj = sB[j];
            float2 Cj = sC[j];
            float dx = fx - Aj.x;
            float dy = fy - Aj.y;
            float e = fmaf(Aj.w, dx * dx,
                      fmaf(Bj.x, dx * dy,
                      fmaf(Bj.y, dy * dy, Bj.z)));
            float alpha = fminf(ex2(e), 0.99f);
            float wgt = T * alpha;
            accR = fmaf(wgt, Bj.w, accR);
            accG = fmaf(wgt, Cj.x, accG);
            accB = fmaf(wgt, Cj.y, accB);
            T = T - wgt;
        }
    }

    if (px < W && py < H) {
        int o = (py * W + px) * 3;
        out[o + 0] = accR;
        out[o + 1] = accG;
        out[o + 2] = accB;
    }
}

extern "C" void kernel_launch(void* const* d_in, const int* in_sizes, int n_in,
                              void* d_out, int out_size) {
    const float* means         = (const float*)d_in[0];
    const float* log_scale     = (const float*)d_in[1];
    const float* rot           = (const float*)d_in[2];
    const float* colour_logits = (const float*)d_in[3];
    const float* opacity_logit = (const float*)d_in[4];
    const float* depth         = (const float*)d_in[5];

    int G = in_sizes[5];
    if (G > MAX_G) G = MAX_G;

    int HW = out_size / 3;
    int W = (int)(sqrt((double)HW) + 0.5);
    if (W <= 0) W = 1;
    int H = HW / W;

    int ntx = (W + TILE_W - 1) / TILE_W;
    int nty = (H + TILE_H - 1) / TILE_H;
    int ntiles = ntx * nty;

    prep_kernel<<<(G + 7) / 8, 256>>>(means, log_scale, rot,
                                      colour_logits, opacity_logit, depth, G);
    raster_kernel<<<ntiles, NTHREADS>>>(W, H, ntx, G, (float*)d_out);
}

// round 8
// speedup vs baseline: 1.1003x; 1.1003x over previous
#include <cuda_runtime.h>
#include <math.h>

#define TILE_W 16
#define TILE_H 8
#define NTHREADS 128
#define NW 4                 // warps per block
#define MAX_G 2048
#define CHUNK 512
#define RPW (CHUNK / NW)     // 128 gaussians per warp per chunk
#define ROUNDS (RPW / 32)    // 4 ballot rounds
#define MAH_CUT 37.0f        // density threshold ~ exp(-18.5)
#define LOG2E 1.4426950408889634f

// ---- device scratch (depth-sorted, packed) ----
__device__ float4 g_pA[MAX_G];   // mx, my, cullR^2, a' (= -0.5*iA*log2e)
__device__ float4 g_pB[MAX_G];   // b' (= -iB*log2e), c' (= -0.5*iC*log2e), log2(opac), colR
__device__ float2 g_pC[MAX_G];   // colG, colB

__device__ __forceinline__ float ex2(float x) {
    float r;
    asm("ex2.approx.ftz.f32 %0, %1;" : "=f"(r) : "f"(x));
    return r;
}

// ---- 1) prep: warp-per-gaussian stable rank + preprocess + scatter ----
__global__ void __launch_bounds__(256) prep_kernel(
        const float* __restrict__ means,
        const float* __restrict__ log_scale,
        const float* __restrict__ rot,
        const float* __restrict__ colour_logits,
        const float* __restrict__ opacity_logit,
        const float* __restrict__ depth,
        int G) {
    __shared__ float sd[MAX_G];
    for (int j = threadIdx.x; j < G; j += blockDim.x) sd[j] = depth[j];
    __syncthreads();

    int w    = threadIdx.x >> 5;
    int lane = threadIdx.x & 31;
    int i = blockIdx.x * 8 + w;
    if (i >= G) return;

    float di = sd[i];
    int r = 0;
    for (int j = lane; j < G; j += 32) {
        float dj = sd[j];
        r += (dj < di) || (dj == di && j < i);
    }
    r = __reduce_add_sync(0xffffffffu, r);

    if (lane == 0) {
        float s2x = __expf(2.f * log_scale[2 * i + 0]);
        float s2y = __expf(2.f * log_scale[2 * i + 1]);
        float s, c;
        __sincosf(rot[i], &s, &c);

        float ca = c * c * s2x + s * s * s2y;
        float cb = c * s * (s2x - s2y);
        float cd = s * s * s2x + c * c * s2y;
        float det = ca * cd - cb * cb;
        float inv = 1.f / det;
        float iA = cd * inv;
        float iB = -cb * inv;
        float iC = ca * inv;

        float opac = 1.f / (1.f + __expf(-opacity_logit[i]));
        float cr  = 1.f / (1.f + __expf(-colour_logits[3 * i + 0]));
        float cg  = 1.f / (1.f + __expf(-colour_logits[3 * i + 1]));
        float cbl = 1.f / (1.f + __expf(-colour_logits[3 * i + 2]));

        float tr = 0.5f * (ca + cd);
        float lmax = tr + sqrtf(fmaxf(tr * tr - det, 0.f));

        g_pA[r] = make_float4(means[2 * i + 0], means[2 * i + 1],
                              MAH_CUT * lmax, -0.5f * iA * LOG2E);
        g_pB[r] = make_float4(-iB * LOG2E, -0.5f * iC * LOG2E,
                              __log2f(opac), cr);
        g_pC[r] = make_float2(cg, cbl);
    }
}

// ---- 2) raster: block per 16x8 tile, 128 threads ----
__global__ void __launch_bounds__(NTHREADS) raster_kernel(int W, int H, int ntx, int G,
                                                          float* __restrict__ out) {
    int tile = blockIdx.x;
    int tx = tile % ntx, ty = tile / ntx;
    int lx = threadIdx.x & (TILE_W - 1);
    int ly = threadIdx.x >> 4;
    int px = tx * TILE_W + lx;
    int py = ty * TILE_H + ly;
    float fx = (float)px, fy = (float)py;

    float x0 = (float)(tx * TILE_W);
    float y0 = (float)(ty * TILE_H);
    float x1 = x0 + (float)(TILE_W - 1);
    float y1 = y0 + (float)(TILE_H - 1);

    int wid  = threadIdx.x >> 5;
    int lane = threadIdx.x & 31;
    unsigned lmask = (1u << lane) - 1u;

    __shared__ float4 sA[CHUNK];
    __shared__ float4 sB[CHUNK];
    __shared__ float2 sC[CHUNK];
    __shared__ int    scnt[NW];

    float T = 1.f, accR = 0.f, accG = 0.f, accB = 0.f;

    for (int c0 = 0; c0 < G; c0 += CHUNK) {
        int gw = c0 + wid * RPW;

        // prefetch cull data: one LDG.128 per gaussian
        float4 Ar[ROUNDS];
#pragma unroll
        for (int r = 0; r < ROUNDS; r++) {
            int g = gw + r * 32 + lane;
            Ar[r] = (g < G) ? g_pA[g] : make_float4(1e30f, 1e30f, -1.f, 0.f);
        }

        // hit tests (registers only)
        bool hr[ROUNDS];
#pragma unroll
        for (int r = 0; r < ROUNDS; r++) {
            float ddx = fmaxf(fmaxf(x0 - Ar[r].x, Ar[r].x - x1), 0.f);
            float ddy = fmaxf(fmaxf(y0 - Ar[r].y, Ar[r].y - y1), 0.f);
            hr[r] = (ddx * ddx + ddy * ddy) <= Ar[r].z;
        }

        // issue predicated B/C loads early so latency overlaps prefix math
        float4 Br[ROUNDS];
        float2 Cr[ROUNDS];
#pragma unroll
        for (int r = 0; r < ROUNDS; r++) {
            if (hr[r]) {
                int g = gw + r * 32 + lane;
                Br[r] = g_pB[g];
                Cr[r] = g_pC[g];
            }
        }

        // ballots + in-warp offsets
        unsigned mask[ROUNDS];
        int offr[ROUNDS];
        int cnt = 0;
#pragma unroll
        for (int r = 0; r < ROUNDS; r++) {
            mask[r] = __ballot_sync(0xffffffffu, hr[r]);
            offr[r] = cnt;
            cnt += __popc(mask[r]);
        }
        if (lane == 0) scnt[wid] = cnt;
        __syncthreads();   // also guards prev-chunk composite reads

        int woff = 0, total = 0;
#pragma unroll
        for (int w = 0; w < NW; w++) {
            int cw = scnt[w];
            woff += (w < wid) ? cw : 0;
            total += cw;
        }

        // scatter compacted data (depth order preserved)
#pragma unroll
        for (int r = 0; r < ROUNDS; r++) {
            if (hr[r]) {
                int idx = woff + offr[r] + __popc(mask[r] & lmask);
                sA[idx] = Ar[r];
                sB[idx] = Br[r];
                sC[idx] = Cr[r];
            }
        }
        __syncthreads();

        // flat branch-free composite
#pragma unroll 4
        for (int j = 0; j < total; j++) {
            float4 Aj = sA[j];
            float4 Bj = sB[j];
            float2 Cj = sC[j];
            float dx = fx - Aj.x;
            float dy = fy - Aj.y;
            float e = fmaf(Aj.w, dx * dx,
                      fmaf(Bj.x, dx * dy,
                      fmaf(Bj.y, dy * dy, Bj.z)));
            float alpha = fminf(ex2(e), 0.99f);
            float wgt = T * alpha;
            accR = fmaf(wgt, Bj.w, accR);
            accG = fmaf(wgt, Cj.x, accG);
            accB = fmaf(wgt, Cj.y, accB);
            T = T - wgt;
        }
    }

    if (px < W && py < H) {
        int o = (py * W + px) * 3;
        out[o + 0] = accR;
        out[o + 1] = accG;
        out[o + 2] = accB;
    }
}

extern "C" void kernel_launch(void* const* d_in, const int* in_sizes, int n_in,
                              void* d_out, int out_size) {
    const float* means         = (const float*)d_in[0];
    const float* log_scale     = (const float*)d_in[1];
    const float* rot           = (const float*)d_in[2];
    const float* colour_logits = (const float*)d_in[3];
    const float* opacity_logit = (const float*)d_in[4];
    const float* depth         = (const float*)d_in[5];

    int G = in_sizes[5];
    if (G > MAX_G) G = MAX_G;

    int HW = out_size / 3;
    int W = (int)(sqrt((double)HW) + 0.5);
    if (W <= 0) W = 1;
    int H = HW / W;

    int ntx = (W + TILE_W - 1) / TILE_W;
    int nty = (H + TILE_H - 1) / TILE_H;
    int ntiles = ntx * nty;

    prep_kernel<<<(G + 7) / 8, 256>>>(means, log_scale, rot,
                                      colour_logits, opacity_logit, depth, G);
    raster_kernel<<<ntiles, NTHREADS>>>(W, H, ntx, G, (float*)d_out);
}